// round 9
// baseline (speedup 1.0000x reference)
#include <cuda_runtime.h>
#include <math.h>
#include <stdint.h>

#define MM 4096
#define DD 2048
#define INV_SQRT_M 0.015625f   // 1/sqrt(4096) exact

#define MV_GRID 512            // blocks; 8 row-triples each
#define MV_TRIP 8
#define CP_GRID 1024           // blocks; 4 rows each
#define CP_ROWS 4

// ---------------- device scratch ----------------
__device__ float g_qt[MM];
__device__ float g_k[MM];
__device__ float g_v[MM];
__device__ float g_it, g_ft, g_ot;
__device__ float g_kqt, g_denom;

__device__ __forceinline__ float dot4(float4 a, float4 b) {
    return a.x * b.x + a.y * b.y + a.z * b.z + a.w * b.w;
}

__device__ __forceinline__ void cp_async16(uint32_t saddr, const void* gaddr) {
    asm volatile("cp.async.cg.shared.global [%0], [%1], 16;"
                 :: "r"(saddr), "l"(gaddr));
}
__device__ __forceinline__ void cp_commit() {
    asm volatile("cp.async.commit_group;");
}
template <int N>
__device__ __forceinline__ void cp_wait() {
    asm volatile("cp.async.wait_group %0;" :: "n"(N));
}

// ---------------- kernel 1: cp.async-pipelined q/k/v matvecs ----------------
// 512 blocks x 256 threads. Block b handles row-triples r = b + p*512, p=0..7.
// Stage = 3 rows x 8KB = 24KB in smem; 2 stages double-buffered via cp.async.
// While triple p is computed/reduced from smem, triple p+1's copies are in
// flight -> loads outstanding ~100% of block lifetime.
__global__ __launch_bounds__(256) void mv_kernel(
    const float* __restrict__ x,
    const float* __restrict__ Wq, const float* __restrict__ bq,
    const float* __restrict__ Wk, const float* __restrict__ bk,
    const float* __restrict__ Wv, const float* __restrict__ bV)
{
    extern __shared__ float sm[];              // [2][3][2048]
    const int b = blockIdx.x;
    const int t = threadIdx.x;

    const float4* x4 = reinterpret_cast<const float4*>(x);
    const float4 x0 = x4[t];
    const float4 x1 = x4[t + 256];

    __shared__ float ws[3][8];

    const uint32_t smbase = (uint32_t)__cvta_generic_to_shared(sm);

    // issue one stage: 6 x 16B cp.async per thread (2 chunks per matrix row)
    auto issue = [&](int p, int stage) {
        const size_t r = (size_t)(b + p * MV_GRID);
        const float* rows[3] = { Wq + r * DD, Wk + r * DD, Wv + r * DD };
        const uint32_t sb = smbase + (uint32_t)stage * 3 * 2048 * 4;
        #pragma unroll
        for (int m = 0; m < 3; m++) {
            #pragma unroll
            for (int c = 0; c < 2; c++) {
                const int fi = (c * 256 + t) * 4;      // float index in row
                cp_async16(sb + (uint32_t)(m * 2048 + fi) * 4, rows[m] + fi);
            }
        }
        cp_commit();
    };

    issue(0, 0);

    #pragma unroll
    for (int p = 0; p < MV_TRIP; p++) {
        if (p + 1 < MV_TRIP) { issue(p + 1, (p + 1) & 1); cp_wait<1>(); }
        else                 { cp_wait<0>(); }
        __syncthreads();

        const float* buf = sm + (p & 1) * 3 * 2048;
        const float4* Aq = reinterpret_cast<const float4*>(buf);
        const float4* Ak = reinterpret_cast<const float4*>(buf + 2048);
        const float4* Av = reinterpret_cast<const float4*>(buf + 4096);

        float sa = dot4(Aq[t], x0) + dot4(Aq[t + 256], x1);
        float sk = dot4(Ak[t], x0) + dot4(Ak[t + 256], x1);
        float sv = dot4(Av[t], x0) + dot4(Av[t + 256], x1);

        #pragma unroll
        for (int o = 16; o > 0; o >>= 1) {
            sa += __shfl_down_sync(0xFFFFFFFFu, sa, o);
            sk += __shfl_down_sync(0xFFFFFFFFu, sk, o);
            sv += __shfl_down_sync(0xFFFFFFFFu, sv, o);
        }
        if ((t & 31) == 0) {
            const int w = t >> 5;
            ws[0][w] = sa; ws[1][w] = sk; ws[2][w] = sv;
        }
        __syncthreads();
        if (t < 8) {
            float ra = ws[0][t], rk = ws[1][t], rv = ws[2][t];
            #pragma unroll
            for (int o = 4; o > 0; o >>= 1) {
                ra += __shfl_down_sync(0xFFu, ra, o, 8);
                rk += __shfl_down_sync(0xFFu, rk, o, 8);
                rv += __shfl_down_sync(0xFFu, rv, o, 8);
            }
            if (t == 0) {
                const int r = b + p * MV_GRID;
                g_qt[r] = ra + bq[r];
                g_k[r]  = INV_SQRT_M * (rk + bk[r]);
                g_v[r]  = rv + bV[r];
            }
        }
        __syncthreads();   // buf + ws safe for reuse
    }
}

// ---------------- kernel 2: gates + n-update + tiny reductions ----------------
__global__ __launch_bounds__(1024) void nred_kernel(
    const float* __restrict__ x,
    const float* __restrict__ Wi, const float* __restrict__ bi,
    const float* __restrict__ Wf, const float* __restrict__ bf,
    const float* __restrict__ Wo, const float* __restrict__ bo,
    const float* __restrict__ n_prev, float* __restrict__ out_n)
{
    const int t = threadIdx.x;
    __shared__ float red[3][32];
    __shared__ float gates[2];

    float si = 0.f, sf = 0.f, so = 0.f;
    #pragma unroll
    for (int u = 0; u < 2; u++) {
        const int i = t + u * 1024;
        const float xv = x[i];
        si += Wi[i] * xv;
        sf += Wf[i] * xv;
        so += Wo[i] * xv;
    }
    #pragma unroll
    for (int o = 16; o > 0; o >>= 1) {
        si += __shfl_down_sync(0xFFFFFFFFu, si, o);
        sf += __shfl_down_sync(0xFFFFFFFFu, sf, o);
        so += __shfl_down_sync(0xFFFFFFFFu, so, o);
    }
    if ((t & 31) == 0) {
        const int w = t >> 5;
        red[0][w] = si; red[1][w] = sf; red[2][w] = so;
    }
    __syncthreads();
    if (t < 32) {
        float a = red[0][t], bb = red[1][t], c = red[2][t];
        #pragma unroll
        for (int o = 16; o > 0; o >>= 1) {
            a  += __shfl_down_sync(0xFFFFFFFFu, a, o);
            bb += __shfl_down_sync(0xFFFFFFFFu, bb, o);
            c  += __shfl_down_sync(0xFFFFFFFFu, c, o);
        }
        if (t == 0) {
            const float itv = expf(a + bi[0]);
            const float ftv = expf(bb + bf[0]);
            const float z   = c + bo[0];
            g_it = itv; g_ft = ftv;
            g_ot = 1.0f / (1.0f + expf(-z));
            gates[0] = itv; gates[1] = ftv;
        }
    }
    __syncthreads();
    const float it = gates[0];
    const float ft = gates[1];

    float kqt = 0.f, nqt = 0.f;
    #pragma unroll
    for (int u = 0; u < MM / 1024; u++) {
        const int i = t + u * 1024;
        const float k = g_k[i];
        const float q = g_qt[i];
        kqt += k * q;
        const float n = ft * n_prev[i] + it * k;
        out_n[i] = n;
        nqt += n * q;
    }
    #pragma unroll
    for (int o = 16; o > 0; o >>= 1) {
        kqt += __shfl_down_sync(0xFFFFFFFFu, kqt, o);
        nqt += __shfl_down_sync(0xFFFFFFFFu, nqt, o);
    }
    __syncthreads();
    if ((t & 31) == 0) { red[0][t >> 5] = kqt; red[1][t >> 5] = nqt; }
    __syncthreads();
    if (t < 32) {
        float a = red[0][t], bb = red[1][t];
        #pragma unroll
        for (int o = 16; o > 0; o >>= 1) {
            a  += __shfl_down_sync(0xFFFFFFFFu, a, o);
            bb += __shfl_down_sync(0xFFFFFFFFu, bb, o);
        }
        if (t == 0) {
            g_kqt = a;
            g_denom = fmaxf(fabsf(bb), 1.0f);
        }
    }
}

// ---------------- kernel 3: cp.async-pipelined cp stream ----------------
// 1024 blocks x 256 threads. Block b handles rows r = b + p*1024, p=0..3.
// Stage = one 16KB row; 2 stages = 32KB smem. k/q cached in registers
// (row-invariant). C written direct with __stcs.
__global__ __launch_bounds__(256) void cp_kernel(
    const float* __restrict__ cp, float* __restrict__ outC,
    float* __restrict__ outH)
{
    extern __shared__ float sm[];              // [2][4096]
    const int b = blockIdx.x;
    const int t = threadIdx.x;

    const float ft  = g_ft;
    const float itg = g_it;
    const float inv = g_ot / g_denom;
    const float kqt = g_kqt;

    float itv[CP_ROWS];
    #pragma unroll
    for (int p = 0; p < CP_ROWS; p++) itv[p] = itg * g_v[b + p * CP_GRID];

    const float4* k4 = reinterpret_cast<const float4*>(g_k);
    const float4* q4 = reinterpret_cast<const float4*>(g_qt);
    float4 kr[4], qr[4];
    #pragma unroll
    for (int c = 0; c < 4; c++) {
        kr[c] = k4[c * 256 + t];
        qr[c] = q4[c * 256 + t];
    }

    __shared__ float ws[8];
    const uint32_t smbase = (uint32_t)__cvta_generic_to_shared(sm);

    auto issue = [&](int p, int stage) {
        const float* src = cp + (size_t)(b + p * CP_GRID) * MM;
        const uint32_t sb = smbase + (uint32_t)stage * 4096 * 4;
        #pragma unroll
        for (int c = 0; c < 4; c++) {
            const int fi = (c * 256 + t) * 4;
            cp_async16(sb + (uint32_t)fi * 4, src + fi);
        }
        cp_commit();
    };

    issue(0, 0);

    #pragma unroll
    for (int p = 0; p < CP_ROWS; p++) {
        if (p + 1 < CP_ROWS) { issue(p + 1, (p + 1) & 1); cp_wait<1>(); }
        else                 { cp_wait<0>(); }
        __syncthreads();

        const int r = b + p * CP_GRID;
        const float4* buf = reinterpret_cast<const float4*>(sm + (p & 1) * 4096);
        float4* O = reinterpret_cast<float4*>(outC + (size_t)r * MM);
        const float iv = itv[p];

        float s = 0.f;
        #pragma unroll
        for (int c = 0; c < 4; c++) {
            const int j = c * 256 + t;
            const float4 cv = buf[j];
            float4 o;
            o.x = ft * cv.x + iv * kr[c].x;
            o.y = ft * cv.y + iv * kr[c].y;
            o.z = ft * cv.z + iv * kr[c].z;
            o.w = ft * cv.w + iv * kr[c].w;
            __stcs(&O[j], o);
            s += dot4(cv, qr[c]);
        }

        #pragma unroll
        for (int o2 = 16; o2 > 0; o2 >>= 1)
            s += __shfl_down_sync(0xFFFFFFFFu, s, o2);
        if ((t & 31) == 0) ws[t >> 5] = s;
        __syncthreads();
        if (t < 8) {
            float a = ws[t];
            #pragma unroll
            for (int o2 = 4; o2 > 0; o2 >>= 1)
                a += __shfl_down_sync(0xFFu, a, o2, 8);
            if (t == 0) outH[r] = inv * (ft * a + iv * kqt);
        }
        __syncthreads();   // buf + ws safe for reuse
    }
}

// ---------------- launch ----------------
extern "C" void kernel_launch(void* const* d_in, const int* in_sizes, int n_in,
                              void* d_out, int out_size)
{
    const float* x      = (const float*)d_in[0];
    const float* cp     = (const float*)d_in[1];
    const float* n_prev = (const float*)d_in[2];
    const float* Wq     = (const float*)d_in[3];
    const float* bq     = (const float*)d_in[4];
    const float* Wk     = (const float*)d_in[5];
    const float* bk     = (const float*)d_in[6];
    const float* Wv     = (const float*)d_in[7];
    const float* bV     = (const float*)d_in[8];
    const float* Wi     = (const float*)d_in[9];
    const float* bi     = (const float*)d_in[10];
    const float* Wf     = (const float*)d_in[11];
    const float* bf     = (const float*)d_in[12];
    const float* Wo     = (const float*)d_in[13];
    const float* bo     = (const float*)d_in[14];

    float* out  = (float*)d_out;
    float* outH = out;                        // ht: M
    float* outC = out + MM;                   // C : M*M
    float* outN = out + MM + (size_t)MM * MM; // n : M

    const int mv_smem = 2 * 3 * 2048 * 4;     // 49152 B dynamic
    const int cp_smem = 2 * 4096 * 4;         // 32768 B dynamic

    // Opt-in: static smem (ws) + 48KB dynamic exceeds the 48KB default
    // carveout; raise the dynamic limit. Attribute set is a host-side,
    // non-stream operation -- legal during graph capture, deterministic.
    cudaFuncSetAttribute(mv_kernel,
                         cudaFuncAttributeMaxDynamicSharedMemorySize, 65536);
    cudaFuncSetAttribute(cp_kernel,
                         cudaFuncAttributeMaxDynamicSharedMemorySize, 65536);

    mv_kernel<<<MV_GRID, 256, mv_smem>>>(x, Wq, bq, Wk, bk, Wv, bV);
    nred_kernel<<<1, 1024>>>(x, Wi, bi, Wf, bf, Wo, bo, n_prev, outN);
    cp_kernel<<<CP_GRID, 256, cp_smem>>>(cp, outC, outH);
}

// round 10
// speedup vs baseline: 1.0464x; 1.0464x over previous
#include <cuda_runtime.h>
#include <math.h>

#define MM 4096
#define DD 2048
#define INV_SQRT_M 0.015625f   // 1/sqrt(4096) exact

// ---------------- device scratch ----------------
__device__ float g_qt[MM];
__device__ float g_k[MM];
__device__ float g_v[MM];
__device__ float g_it, g_ft, g_ot;
__device__ float g_kqt, g_denom;
__device__ float g_pmv[3][MM][4];   // (matrix, row, chunk) matvec partials
__device__ float g_pcp[MM][8];      // (row, chunk) cp@qt partials

__device__ __forceinline__ float dot4(float4 a, float4 b) {
    return a.x * b.x + a.y * b.y + a.z * b.z + a.w * b.w;
}

// ---------------- kernel 1: sync-free matvec partials ----------------
// One warp owns one 512-float chunk of one W row. 4 front-batched streaming
// loads, warp-shuffle dot, one scalar partial store. No smem, no syncthreads.
// 49152 warps = 6144 blocks x 256 threads.
__global__ __launch_bounds__(256) void mv_partial(
    const float* __restrict__ x,
    const float* __restrict__ Wq,
    const float* __restrict__ Wk,
    const float* __restrict__ Wv)
{
    const int w    = blockIdx.x * 8 + (threadIdx.x >> 5);
    const int lane = threadIdx.x & 31;
    const int row  = w / 12;
    const int rem  = w - row * 12;
    const int m    = rem >> 2;       // matrix 0..2
    const int ch   = rem & 3;        // chunk 0..3

    const float* W = (m == 0) ? Wq : (m == 1) ? Wk : Wv;
    const float4* W4 = reinterpret_cast<const float4*>(W + (size_t)row * DD + ch * 512);
    const float4* x4 = reinterpret_cast<const float4*>(x + ch * 512);

    // 4 independent streaming loads front-batched
    float4 w0 = __ldcs(&W4[lane]);
    float4 w1 = __ldcs(&W4[lane + 32]);
    float4 w2 = __ldcs(&W4[lane + 64]);
    float4 w3 = __ldcs(&W4[lane + 96]);
    float4 xa = x4[lane];
    float4 xb = x4[lane + 32];
    float4 xc = x4[lane + 64];
    float4 xd = x4[lane + 96];

    float s = dot4(w0, xa) + dot4(w1, xb) + dot4(w2, xc) + dot4(w3, xd);
    #pragma unroll
    for (int o = 16; o > 0; o >>= 1) s += __shfl_down_sync(0xFFFFFFFFu, s, o);
    if (lane == 0) g_pmv[m][row][ch] = s;
}

// ---------------- kernel 2: fold matvec partials -> qt, k, v ----------------
__global__ __launch_bounds__(512) void qkv_reduce(
    const float* __restrict__ bq,
    const float* __restrict__ bk,
    const float* __restrict__ bV)
{
    const int r = blockIdx.x * 512 + threadIdx.x;
    const float4 pq = *reinterpret_cast<const float4*>(g_pmv[0][r]);
    const float4 pk = *reinterpret_cast<const float4*>(g_pmv[1][r]);
    const float4 pv = *reinterpret_cast<const float4*>(g_pmv[2][r]);
    g_qt[r] = (pq.x + pq.y) + (pq.z + pq.w) + bq[r];
    g_k[r]  = INV_SQRT_M * ((pk.x + pk.y) + (pk.z + pk.w) + bk[r]);
    g_v[r]  = (pv.x + pv.y) + (pv.z + pv.w) + bV[r];
}

// ---------------- kernel 3: gates + n-update + tiny reductions ----------------
__global__ __launch_bounds__(1024) void nred_kernel(
    const float* __restrict__ x,
    const float* __restrict__ Wi, const float* __restrict__ bi,
    const float* __restrict__ Wf, const float* __restrict__ bf,
    const float* __restrict__ Wo, const float* __restrict__ bo,
    const float* __restrict__ n_prev, float* __restrict__ out_n)
{
    const int t = threadIdx.x;
    __shared__ float red[3][32];
    __shared__ float gates[2];

    float si = 0.f, sf = 0.f, so = 0.f;
    #pragma unroll
    for (int u = 0; u < 2; u++) {
        const int i = t + u * 1024;
        const float xv = x[i];
        si += Wi[i] * xv;
        sf += Wf[i] * xv;
        so += Wo[i] * xv;
    }
    #pragma unroll
    for (int o = 16; o > 0; o >>= 1) {
        si += __shfl_down_sync(0xFFFFFFFFu, si, o);
        sf += __shfl_down_sync(0xFFFFFFFFu, sf, o);
        so += __shfl_down_sync(0xFFFFFFFFu, so, o);
    }
    if ((t & 31) == 0) {
        const int w = t >> 5;
        red[0][w] = si; red[1][w] = sf; red[2][w] = so;
    }
    __syncthreads();
    if (t < 32) {
        float a = red[0][t], bb = red[1][t], c = red[2][t];
        #pragma unroll
        for (int o = 16; o > 0; o >>= 1) {
            a  += __shfl_down_sync(0xFFFFFFFFu, a, o);
            bb += __shfl_down_sync(0xFFFFFFFFu, bb, o);
            c  += __shfl_down_sync(0xFFFFFFFFu, c, o);
        }
        if (t == 0) {
            const float itv = expf(a + bi[0]);
            const float ftv = expf(bb + bf[0]);
            const float z   = c + bo[0];
            g_it = itv; g_ft = ftv;
            g_ot = 1.0f / (1.0f + expf(-z));
            gates[0] = itv; gates[1] = ftv;
        }
    }
    __syncthreads();
    const float it = gates[0];
    const float ft = gates[1];

    float kqt = 0.f, nqt = 0.f;
    #pragma unroll
    for (int u = 0; u < MM / 1024; u++) {
        const int i = t + u * 1024;
        const float k = g_k[i];
        const float q = g_qt[i];
        kqt += k * q;
        const float n = ft * n_prev[i] + it * k;
        out_n[i] = n;
        nqt += n * q;
    }
    #pragma unroll
    for (int o = 16; o > 0; o >>= 1) {
        kqt += __shfl_down_sync(0xFFFFFFFFu, kqt, o);
        nqt += __shfl_down_sync(0xFFFFFFFFu, nqt, o);
    }
    __syncthreads();
    if ((t & 31) == 0) { red[0][t >> 5] = kqt; red[1][t >> 5] = nqt; }
    __syncthreads();
    if (t < 32) {
        float a = red[0][t], bb = red[1][t];
        #pragma unroll
        for (int o = 16; o > 0; o >>= 1) {
            a  += __shfl_down_sync(0xFFFFFFFFu, a, o);
            bb += __shfl_down_sync(0xFFFFFFFFu, bb, o);
        }
        if (t == 0) {
            g_kqt = a;
            g_denom = fmaxf(fabsf(bb), 1.0f);
        }
    }
}

// ---------------- kernel 4: sync-free cp stream + dot partials ----------------
// One warp owns one 512-float chunk of one cp row: elementwise C write +
// warp-shuffle partial of cp@qt. No smem, no syncthreads.
// 32768 warps = 4096 blocks x 256 threads.
__global__ __launch_bounds__(256) void cp_partial(
    const float* __restrict__ cp, float* __restrict__ outC)
{
    const int w    = blockIdx.x * 8 + (threadIdx.x >> 5);
    const int lane = threadIdx.x & 31;
    const int row  = w >> 3;
    const int ch   = w & 7;

    const float ft = g_ft;
    const float iv = g_it * g_v[row];

    const size_t base = (size_t)row * MM + ch * 512;
    const float4* P  = reinterpret_cast<const float4*>(cp + base);
    float4*       O  = reinterpret_cast<float4*>(outC + base);
    const float4* k4 = reinterpret_cast<const float4*>(g_k + ch * 512);
    const float4* q4 = reinterpret_cast<const float4*>(g_qt + ch * 512);

    // 4 independent streaming loads front-batched
    float4 c0 = __ldcs(&P[lane]);
    float4 c1 = __ldcs(&P[lane + 32]);
    float4 c2 = __ldcs(&P[lane + 64]);
    float4 c3 = __ldcs(&P[lane + 96]);
    float4 k0 = k4[lane], k1 = k4[lane + 32], k2 = k4[lane + 64], k3 = k4[lane + 96];
    float4 q0 = q4[lane], q1 = q4[lane + 32], q2 = q4[lane + 64], q3 = q4[lane + 96];

    float4 o;
    o.x = ft * c0.x + iv * k0.x; o.y = ft * c0.y + iv * k0.y;
    o.z = ft * c0.z + iv * k0.z; o.w = ft * c0.w + iv * k0.w;
    __stcs(&O[lane], o);
    o.x = ft * c1.x + iv * k1.x; o.y = ft * c1.y + iv * k1.y;
    o.z = ft * c1.z + iv * k1.z; o.w = ft * c1.w + iv * k1.w;
    __stcs(&O[lane + 32], o);
    o.x = ft * c2.x + iv * k2.x; o.y = ft * c2.y + iv * k2.y;
    o.z = ft * c2.z + iv * k2.z; o.w = ft * c2.w + iv * k2.w;
    __stcs(&O[lane + 64], o);
    o.x = ft * c3.x + iv * k3.x; o.y = ft * c3.y + iv * k3.y;
    o.z = ft * c3.z + iv * k3.z; o.w = ft * c3.w + iv * k3.w;
    __stcs(&O[lane + 96], o);

    float s = dot4(c0, q0) + dot4(c1, q1) + dot4(c2, q2) + dot4(c3, q3);
    #pragma unroll
    for (int o2 = 16; o2 > 0; o2 >>= 1) s += __shfl_down_sync(0xFFFFFFFFu, s, o2);
    if (lane == 0) g_pcp[row][ch] = s;
}

// ---------------- kernel 5: fold cp partials -> ht ----------------
__global__ __launch_bounds__(1024) void hred_kernel(float* __restrict__ outH)
{
    const int r = blockIdx.x * 1024 + threadIdx.x;
    const float4 p0 = *reinterpret_cast<const float4*>(&g_pcp[r][0]);
    const float4 p1 = *reinterpret_cast<const float4*>(&g_pcp[r][4]);
    const float s = ((p0.x + p0.y) + (p0.z + p0.w))
                  + ((p1.x + p1.y) + (p1.z + p1.w));
    const float iv = g_it * g_v[r];
    outH[r] = (g_ot / g_denom) * (g_ft * s + iv * g_kqt);
}

// ---------------- launch ----------------
extern "C" void kernel_launch(void* const* d_in, const int* in_sizes, int n_in,
                              void* d_out, int out_size)
{
    const float* x      = (const float*)d_in[0];
    const float* cp     = (const float*)d_in[1];
    const float* n_prev = (const float*)d_in[2];
    const float* Wq     = (const float*)d_in[3];
    const float* bq     = (const float*)d_in[4];
    const float* Wk     = (const float*)d_in[5];
    const float* bk     = (const float*)d_in[6];
    const float* Wv     = (const float*)d_in[7];
    const float* bV     = (const float*)d_in[8];
    const float* Wi     = (const float*)d_in[9];
    const float* bi     = (const float*)d_in[10];
    const float* Wf     = (const float*)d_in[11];
    const float* bf     = (const float*)d_in[12];
    const float* Wo     = (const float*)d_in[13];
    const float* bo     = (const float*)d_in[14];

    float* out  = (float*)d_out;
    float* outH = out;                        // ht: M
    float* outC = out + MM;                   // C : M*M
    float* outN = out + MM + (size_t)MM * MM; // n : M

    mv_partial<<<6144, 256>>>(x, Wq, Wk, Wv);
    qkv_reduce<<<MM / 512, 512>>>(bq, bk, bV);
    nred_kernel<<<1, 1024>>>(x, Wi, bi, Wf, bf, Wo, bo, n_prev, outN);
    cp_partial<<<4096, 256>>>(cp, outC);
    hred_kernel<<<MM / 1024, 1024>>>(outH);
}

// round 11
// speedup vs baseline: 1.0566x; 1.0098x over previous
#include <cuda_runtime.h>
#include <math.h>

#define MM 4096
#define DD 2048
#define INV_SQRT_M 0.015625f   // 1/sqrt(4096) exact

// ---------------- device scratch ----------------
__device__ float g_qt[MM];
__device__ float g_k[MM];
__device__ float g_v[MM];
__device__ float g_it, g_ft, g_ot;
__device__ float g_kqt, g_denom;
__device__ float g_pcp[MM][8];      // (row, chunk) cp@qt partials

__device__ __forceinline__ float dot4(float4 a, float4 b) {
    return a.x * b.x + a.y * b.y + a.z * b.z + a.w * b.w;
}

// ---------------- kernel 1: fused q/k/v matvecs (round-6 best: 19.7us) ----------------
// grid = MM blocks x 256 threads; block b computes row b of Wq, Wk, Wv.
// 6 front-batched streaming loads per thread (MLP=6), block reduce.
__global__ __launch_bounds__(256) void mv_kernel(
    const float* __restrict__ x,
    const float* __restrict__ Wq, const float* __restrict__ bq,
    const float* __restrict__ Wk, const float* __restrict__ bk,
    const float* __restrict__ Wv, const float* __restrict__ bV)
{
    const int b = blockIdx.x;
    const int t = threadIdx.x;

    const float4* A4 = reinterpret_cast<const float4*>(Wq + (size_t)b * DD);
    const float4* B4 = reinterpret_cast<const float4*>(Wk + (size_t)b * DD);
    const float4* C4 = reinterpret_cast<const float4*>(Wv + (size_t)b * DD);
    const float4* x4 = reinterpret_cast<const float4*>(x);

    // 6 independent streaming loads, front-batched (MLP=6)
    float4 a0 = __ldcs(&A4[t]);
    float4 a1 = __ldcs(&A4[t + 256]);
    float4 k0 = __ldcs(&B4[t]);
    float4 k1 = __ldcs(&B4[t + 256]);
    float4 v0 = __ldcs(&C4[t]);
    float4 v1 = __ldcs(&C4[t + 256]);
    float4 x0 = x4[t];
    float4 x1 = x4[t + 256];

    float sa = dot4(a0, x0) + dot4(a1, x1);
    float sk = dot4(k0, x0) + dot4(k1, x1);
    float sv = dot4(v0, x0) + dot4(v1, x1);

    #pragma unroll
    for (int o = 16; o > 0; o >>= 1) {
        sa += __shfl_down_sync(0xFFFFFFFFu, sa, o);
        sk += __shfl_down_sync(0xFFFFFFFFu, sk, o);
        sv += __shfl_down_sync(0xFFFFFFFFu, sv, o);
    }

    __shared__ float wsa[8], wsk[8], wsv[8];
    if ((t & 31) == 0) {
        const int w = t >> 5;
        wsa[w] = sa; wsk[w] = sk; wsv[w] = sv;
    }
    __syncthreads();
    if (t < 8) {
        float ra = wsa[t], rk = wsk[t], rv = wsv[t];
        #pragma unroll
        for (int o = 4; o > 0; o >>= 1) {
            ra += __shfl_down_sync(0xFFu, ra, o, 8);
            rk += __shfl_down_sync(0xFFu, rk, o, 8);
            rv += __shfl_down_sync(0xFFu, rv, o, 8);
        }
        if (t == 0) {
            g_qt[b] = ra + bq[b];
            g_k[b]  = INV_SQRT_M * (rk + bk[b]);
            g_v[b]  = rv + bV[b];
        }
    }
}

// ---------------- kernel 2: gates + n-update + tiny reductions ----------------
__global__ __launch_bounds__(1024) void nred_kernel(
    const float* __restrict__ x,
    const float* __restrict__ Wi, const float* __restrict__ bi,
    const float* __restrict__ Wf, const float* __restrict__ bf,
    const float* __restrict__ Wo, const float* __restrict__ bo,
    const float* __restrict__ n_prev, float* __restrict__ out_n)
{
    const int t = threadIdx.x;
    __shared__ float red[3][32];
    __shared__ float gates[2];

    float si = 0.f, sf = 0.f, so = 0.f;
    #pragma unroll
    for (int u = 0; u < 2; u++) {
        const int i = t + u * 1024;
        const float xv = x[i];
        si += Wi[i] * xv;
        sf += Wf[i] * xv;
        so += Wo[i] * xv;
    }
    #pragma unroll
    for (int o = 16; o > 0; o >>= 1) {
        si += __shfl_down_sync(0xFFFFFFFFu, si, o);
        sf += __shfl_down_sync(0xFFFFFFFFu, sf, o);
        so += __shfl_down_sync(0xFFFFFFFFu, so, o);
    }
    if ((t & 31) == 0) {
        const int w = t >> 5;
        red[0][w] = si; red[1][w] = sf; red[2][w] = so;
    }
    __syncthreads();
    if (t < 32) {
        float a = red[0][t], bb = red[1][t], c = red[2][t];
        #pragma unroll
        for (int o = 16; o > 0; o >>= 1) {
            a  += __shfl_down_sync(0xFFFFFFFFu, a, o);
            bb += __shfl_down_sync(0xFFFFFFFFu, bb, o);
            c  += __shfl_down_sync(0xFFFFFFFFu, c, o);
        }
        if (t == 0) {
            const float itv = expf(a + bi[0]);
            const float ftv = expf(bb + bf[0]);
            const float z   = c + bo[0];
            g_it = itv; g_ft = ftv;
            g_ot = 1.0f / (1.0f + expf(-z));
            gates[0] = itv; gates[1] = ftv;
        }
    }
    __syncthreads();
    const float it = gates[0];
    const float ft = gates[1];

    float kqt = 0.f, nqt = 0.f;
    #pragma unroll
    for (int u = 0; u < MM / 1024; u++) {
        const int i = t + u * 1024;
        const float k = g_k[i];
        const float q = g_qt[i];
        kqt += k * q;
        const float n = ft * n_prev[i] + it * k;
        out_n[i] = n;
        nqt += n * q;
    }
    #pragma unroll
    for (int o = 16; o > 0; o >>= 1) {
        kqt += __shfl_down_sync(0xFFFFFFFFu, kqt, o);
        nqt += __shfl_down_sync(0xFFFFFFFFu, nqt, o);
    }
    __syncthreads();
    if ((t & 31) == 0) { red[0][t >> 5] = kqt; red[1][t >> 5] = nqt; }
    __syncthreads();
    if (t < 32) {
        float a = red[0][t], bb = red[1][t];
        #pragma unroll
        for (int o = 16; o > 0; o >>= 1) {
            a  += __shfl_down_sync(0xFFFFFFFFu, a, o);
            bb += __shfl_down_sync(0xFFFFFFFFu, bb, o);
        }
        if (t == 0) {
            g_kqt = a;
            g_denom = fmaxf(fabsf(bb), 1.0f);
        }
    }
}

// ---------------- kernel 3: sync-free cp stream + dot partials (20.3us) ----------------
// One warp owns one 512-float chunk of one cp row: elementwise C write +
// warp-shuffle partial of cp@qt. No smem, no syncthreads.
// 32768 warps = 4096 blocks x 256 threads; all 8 warps of a block share a row.
__global__ __launch_bounds__(256) void cp_partial(
    const float* __restrict__ cp, float* __restrict__ outC)
{
    const int w    = blockIdx.x * 8 + (threadIdx.x >> 5);
    const int lane = threadIdx.x & 31;
    const int row  = w >> 3;
    const int ch   = w & 7;

    const float ft = g_ft;
    const float iv = g_it * g_v[row];

    const size_t base = (size_t)row * MM + ch * 512;
    const float4* P  = reinterpret_cast<const float4*>(cp + base);
    float4*       O  = reinterpret_cast<float4*>(outC + base);
    const float4* k4 = reinterpret_cast<const float4*>(g_k + ch * 512);
    const float4* q4 = reinterpret_cast<const float4*>(g_qt + ch * 512);

    // 4 independent streaming loads front-batched
    float4 c0 = __ldcs(&P[lane]);
    float4 c1 = __ldcs(&P[lane + 32]);
    float4 c2 = __ldcs(&P[lane + 64]);
    float4 c3 = __ldcs(&P[lane + 96]);
    float4 k0 = k4[lane], k1 = k4[lane + 32], k2 = k4[lane + 64], k3 = k4[lane + 96];
    float4 q0 = q4[lane], q1 = q4[lane + 32], q2 = q4[lane + 64], q3 = q4[lane + 96];

    float4 o;
    o.x = ft * c0.x + iv * k0.x; o.y = ft * c0.y + iv * k0.y;
    o.z = ft * c0.z + iv * k0.z; o.w = ft * c0.w + iv * k0.w;
    __stcs(&O[lane], o);
    o.x = ft * c1.x + iv * k1.x; o.y = ft * c1.y + iv * k1.y;
    o.z = ft * c1.z + iv * k1.z; o.w = ft * c1.w + iv * k1.w;
    __stcs(&O[lane + 32], o);
    o.x = ft * c2.x + iv * k2.x; o.y = ft * c2.y + iv * k2.y;
    o.z = ft * c2.z + iv * k2.z; o.w = ft * c2.w + iv * k2.w;
    __stcs(&O[lane + 64], o);
    o.x = ft * c3.x + iv * k3.x; o.y = ft * c3.y + iv * k3.y;
    o.z = ft * c3.z + iv * k3.z; o.w = ft * c3.w + iv * k3.w;
    __stcs(&O[lane + 96], o);

    float s = dot4(c0, q0) + dot4(c1, q1) + dot4(c2, q2) + dot4(c3, q3);
    #pragma unroll
    for (int o2 = 16; o2 > 0; o2 >>= 1) s += __shfl_down_sync(0xFFFFFFFFu, s, o2);
    if (lane == 0) g_pcp[row][ch] = s;
}

// ---------------- kernel 4: fold cp partials -> ht ----------------
__global__ __launch_bounds__(1024) void hred_kernel(float* __restrict__ outH)
{
    const int r = blockIdx.x * 1024 + threadIdx.x;
    const float4 p0 = *reinterpret_cast<const float4*>(&g_pcp[r][0]);
    const float4 p1 = *reinterpret_cast<const float4*>(&g_pcp[r][4]);
    const float s = ((p0.x + p0.y) + (p0.z + p0.w))
                  + ((p1.x + p1.y) + (p1.z + p1.w));
    const float iv = g_it * g_v[r];
    outH[r] = (g_ot / g_denom) * (g_ft * s + iv * g_kqt);
}

// ---------------- launch ----------------
extern "C" void kernel_launch(void* const* d_in, const int* in_sizes, int n_in,
                              void* d_out, int out_size)
{
    const float* x      = (const float*)d_in[0];
    const float* cp     = (const float*)d_in[1];
    const float* n_prev = (const float*)d_in[2];
    const float* Wq     = (const float*)d_in[3];
    const float* bq     = (const float*)d_in[4];
    const float* Wk     = (const float*)d_in[5];
    const float* bk     = (const float*)d_in[6];
    const float* Wv     = (const float*)d_in[7];
    const float* bV     = (const float*)d_in[8];
    const float* Wi     = (const float*)d_in[9];
    const float* bi     = (const float*)d_in[10];
    const float* Wf     = (const float*)d_in[11];
    const float* bf     = (const float*)d_in[12];
    const float* Wo     = (const float*)d_in[13];
    const float* bo     = (const float*)d_in[14];

    float* out  = (float*)d_out;
    float* outH = out;                        // ht: M
    float* outC = out + MM;                   // C : M*M
    float* outN = out + MM + (size_t)MM * MM; // n : M

    mv_kernel<<<MM, 256>>>(x, Wq, bq, Wk, bk, Wv, bV);
    nred_kernel<<<1, 1024>>>(x, Wi, bi, Wf, bf, Wo, bo, n_prev, outN);
    cp_partial<<<4096, 256>>>(cp, outC);
    hred_kernel<<<MM / 1024, 1024>>>(outH);
}